// round 12
// baseline (speedup 1.0000x reference)
#include <cuda_runtime.h>
#include <cstdint>

#define N_NODES 100000
#define N_EDGES 1600000
#define DIM     128
#define T_NODES 4096
#define P_PAIRS 131072
#define HP      256
#define DOUT    128
#define ZDIM    64

// ---------------- scratch (static device globals; no allocation) ----------------
__device__ int   g_cnt[N_NODES];
__device__ int   g_rowptr[N_NODES + 1];
__device__ int   g_cursor[N_NODES];
__device__ int   g_col[N_EDGES];
__device__ float g_invdeg[N_NODES];
__device__ unsigned char g_flag[N_NODES];
__device__ unsigned char g_tflag[N_NODES];
__device__ float g_pe[N_NODES * 4];
__device__ float g_zb[HP];
__device__ float g_wf[DIM * HP];                    // W2c @ Wp1[0:128]
__device__ float g_buf1[(size_t)N_NODES * DIM];
__device__ float g_buf2[(size_t)N_NODES * DIM];
__device__ float g_tbuf[(size_t)T_NODES * DIM];

// ---------------- tf32 / mma helpers ----------------
__device__ __forceinline__ unsigned f2tf(float f) {
    unsigned u;
    asm("cvt.rna.tf32.f32 %0, %1;" : "=r"(u) : "f"(f));
    return u;
}
__device__ __forceinline__ void mma8(float* c, const unsigned* a, const unsigned* b) {
    asm volatile(
        "mma.sync.aligned.m16n8k8.row.col.f32.tf32.tf32.f32 "
        "{%0,%1,%2,%3},{%4,%5,%6,%7},{%8,%9},{%0,%1,%2,%3};"
        : "+f"(c[0]), "+f"(c[1]), "+f"(c[2]), "+f"(c[3])
        : "r"(a[0]), "r"(a[1]), "r"(a[2]), "r"(a[3]), "r"(b[0]), "r"(b[1]));
}
__device__ __forceinline__ void ldsm4(unsigned* r, const unsigned* p) {
    unsigned addr = (unsigned)__cvta_generic_to_shared(p);
    asm volatile("ldmatrix.sync.aligned.m8n8.x4.shared.b16 {%0,%1,%2,%3}, [%4];"
                 : "=r"(r[0]), "=r"(r[1]), "=r"(r[2]), "=r"(r[3]) : "r"(addr));
}

// ---------------- CSR build ----------------
__global__ void k_zero_cnt() {
    int i = blockIdx.x * blockDim.x + threadIdx.x;
    if (i < N_NODES) { g_cnt[i] = 0; g_flag[i] = 0; g_tflag[i] = 0; }
}

__global__ void k_count(const int* __restrict__ dst) {
    int e = blockIdx.x * blockDim.x + threadIdx.x;
    if (e < N_EDGES) atomicAdd(&g_cnt[dst[e]], 1);
}

__global__ void k_scan() {
    __shared__ int sums[1024];
    const int CH = (N_NODES + 1024) / 1024;
    int t = threadIdx.x;
    int base = t * CH;
    int s = 0;
    for (int i = 0; i < CH; i++) {
        int idx = base + i;
        if (idx < N_NODES) s += g_cnt[idx];
    }
    sums[t] = s;
    __syncthreads();
    for (int off = 1; off < 1024; off <<= 1) {
        int v = (t >= off) ? sums[t - off] : 0;
        __syncthreads();
        sums[t] += v;
        __syncthreads();
    }
    int run = sums[t] - s;
    for (int i = 0; i < CH; i++) {
        int idx = base + i;
        if (idx <= N_NODES) g_rowptr[idx] = run;
        if (idx < N_NODES) run += g_cnt[idx];
    }
}

__global__ void k_prep() {
    int i = blockIdx.x * blockDim.x + threadIdx.x;
    if (i < N_NODES) {
        g_cursor[i] = g_rowptr[i];
        int c = g_cnt[i];
        g_invdeg[i] = 1.0f / (float)(c > 0 ? c : 1);
    }
}

__global__ void k_fill(const int* __restrict__ src, const int* __restrict__ dst) {
    int e = blockIdx.x * blockDim.x + threadIdx.x;
    if (e < N_EDGES) {
        int pos = atomicAdd(&g_cursor[dst[e]], 1);
        g_col[pos] = src[e];
    }
}

__global__ void k_flag(const int* __restrict__ pair_s, const float* __restrict__ mask) {
    int i = blockIdx.x * blockDim.x + threadIdx.x;
    if (i < P_PAIRS && mask[i] != 0.f) g_flag[pair_s[i]] = 1;
}

// mark in-neighbors of target nodes (rows of h_t actually consumed by agg_target)
__global__ void k_tflag(const int* __restrict__ tgt) {
    int b = blockIdx.x * blockDim.x + threadIdx.x;
    if (b >= T_NODES) return;
    int n = tgt[b];
    int e = g_rowptr[n + 1];
    for (int i = g_rowptr[n]; i < e; i++) g_tflag[g_col[i]] = 1;
}

// ---------------- tiny precomputes ----------------
__global__ void k_pe(const float* __restrict__ pos_enc, const float* __restrict__ Wpe) {
    int n = blockIdx.x * blockDim.x + threadIdx.x;
    if (n >= N_NODES) return;
    float4 p = *(const float4*)&pos_enc[n * 4];
#pragma unroll
    for (int i = 0; i < 4; i++) {
        g_pe[n * 4 + i] = p.x * Wpe[i * 4 + 0] + p.y * Wpe[i * 4 + 1] +
                          p.z * Wpe[i * 4 + 2] + p.w * Wpe[i * 4 + 3];
    }
}

__global__ void k_zb(const float* __restrict__ z, const float* __restrict__ Wp1,
                     const float* __restrict__ bp1) {
    int j = threadIdx.x;
    float acc = bp1[j];
    for (int i = 0; i < ZDIM; i++) acc = fmaf(z[i], Wp1[(128 + i) * HP + j], acc);
    g_zb[j] = acc;
}

__global__ void k_wf(const float* __restrict__ W2c, const float* __restrict__ Wp1) {
    int i = blockIdx.x;
    int j = threadIdx.x;
    float acc = 0.f;
    for (int d = 0; d < DIM; d++) acc = fmaf(W2c[i * DIM + d], Wp1[d * HP + j], acc);
    g_wf[i * HP + j] = acc;
}

// ---------------- tf32 GEMM (R10-proven, ldmatrix): C = (relu?)(A @ B) -------------
#define AS_STR 36
#define BT_STR 36
__global__ void __launch_bounds__(256)
k_gemm_tf32(const float* __restrict__ A, const float* __restrict__ B,
            float* __restrict__ C, int M, int relu) {
    __shared__ unsigned As[128 * AS_STR];
    __shared__ unsigned Bst[128 * BT_STR];
    int m0 = blockIdx.x * 128;
    int tid = threadIdx.x;
    int lane = tid & 31, wid = tid >> 5;
    int wm = wid & 3, wn = wid >> 2;      // rows wm*32, cols wn*64
    int gid = lane >> 2, tig = lane & 3;

    float c[2][8][4];
#pragma unroll
    for (int mt = 0; mt < 2; mt++)
#pragma unroll
        for (int nt = 0; nt < 8; nt++)
#pragma unroll
            for (int q = 0; q < 4; q++) c[mt][nt][q] = 0.f;

    int ar = tid >> 1, acb = (tid & 1) * 16;   // A stage: 128 rows x 32 k
    int bn = tid & 127, bkh = (tid >> 7) * 16; // B stage: 128 n x 32 k (transposed)

    const unsigned* pa0 = &As[(wm * 32 + (lane & 15)) * AS_STR + ((lane >> 4) << 2)];
    const unsigned* pa1 = pa0 + 16 * AS_STR;
    const unsigned* pb  = &Bst[(wn * 64 + ((lane >> 4) << 3) + (lane & 7)) * BT_STR +
                               (((lane >> 3) & 1) << 2)];

    for (int kc = 0; kc < 128; kc += 32) {
        {
            int grow = m0 + ar;
#pragma unroll
            for (int q = 0; q < 2; q++) {
                float4 v0 = (grow < M)
                    ? *(const float4*)&A[(size_t)grow * 128 + kc + acb + q * 8]
                    : make_float4(0.f, 0.f, 0.f, 0.f);
                float4 v1 = (grow < M)
                    ? *(const float4*)&A[(size_t)grow * 128 + kc + acb + q * 8 + 4]
                    : make_float4(0.f, 0.f, 0.f, 0.f);
                *(uint4*)&As[ar * AS_STR + acb + q * 8] =
                    make_uint4(f2tf(v0.x), f2tf(v0.y), f2tf(v0.z), f2tf(v0.w));
                *(uint4*)&As[ar * AS_STR + acb + q * 8 + 4] =
                    make_uint4(f2tf(v1.x), f2tf(v1.y), f2tf(v1.z), f2tf(v1.w));
            }
#pragma unroll
            for (int q = 0; q < 4; q++) {
                int kk = bkh + q * 4;
                uint4 u;
                u.x = f2tf(B[(size_t)(kc + kk + 0) * 128 + bn]);
                u.y = f2tf(B[(size_t)(kc + kk + 1) * 128 + bn]);
                u.z = f2tf(B[(size_t)(kc + kk + 2) * 128 + bn]);
                u.w = f2tf(B[(size_t)(kc + kk + 3) * 128 + bn]);
                *(uint4*)&Bst[bn * BT_STR + kk] = u;
            }
        }
        __syncthreads();
#pragma unroll
        for (int ks = 0; ks < 4; ks++) {
            int kb = ks * 8;
            unsigned a[2][4], b[8][2];
            ldsm4(a[0], pa0 + kb);
            ldsm4(a[1], pa1 + kb);
#pragma unroll
            for (int p = 0; p < 4; p++) {
                unsigned t4[4];
                ldsm4(t4, pb + p * 16 * BT_STR + kb);
                b[2 * p][0] = t4[0]; b[2 * p][1] = t4[1];
                b[2 * p + 1][0] = t4[2]; b[2 * p + 1][1] = t4[3];
            }
#pragma unroll
            for (int mt = 0; mt < 2; mt++)
#pragma unroll
                for (int nt = 0; nt < 8; nt++) mma8(c[mt][nt], a[mt], b[nt]);
        }
        __syncthreads();
    }

#pragma unroll
    for (int mt = 0; mt < 2; mt++) {
        int r = m0 + wm * 32 + mt * 16 + gid;
#pragma unroll
        for (int nt = 0; nt < 8; nt++) {
            int col = wn * 64 + nt * 8 + 2 * tig;
            float2 v0 = make_float2(c[mt][nt][0], c[mt][nt][1]);
            float2 v1 = make_float2(c[mt][nt][2], c[mt][nt][3]);
            if (relu) {
                v0.x = fmaxf(v0.x, 0.f); v0.y = fmaxf(v0.y, 0.f);
                v1.x = fmaxf(v1.x, 0.f); v1.y = fmaxf(v1.y, 0.f);
            }
            if (r < M)     *(float2*)&C[(size_t)r * 128 + col] = v0;
            if (r + 8 < M) *(float2*)&C[(size_t)(r + 8) * 128 + col] = v1;
        }
    }
}

// ---------------- CSR gather-aggregation: warp per node, float4 lanes ----------------
__device__ __forceinline__ void agg_node(const float* __restrict__ in, int n, int lane,
                                         float4& r) {
    int s = g_rowptr[n], e = g_rowptr[n + 1];
    float4 a0 = make_float4(0.f, 0.f, 0.f, 0.f), a1 = a0, a2 = a0, a3 = a0;
    int i = s;
    for (; i + 4 <= e; i += 4) {
        int c0 = g_col[i], c1 = g_col[i + 1], c2 = g_col[i + 2], c3 = g_col[i + 3];
        float4 v0 = *(const float4*)&in[(size_t)c0 * 128 + lane * 4];
        float4 v1 = *(const float4*)&in[(size_t)c1 * 128 + lane * 4];
        float4 v2 = *(const float4*)&in[(size_t)c2 * 128 + lane * 4];
        float4 v3 = *(const float4*)&in[(size_t)c3 * 128 + lane * 4];
        a0.x += v0.x; a0.y += v0.y; a0.z += v0.z; a0.w += v0.w;
        a1.x += v1.x; a1.y += v1.y; a1.z += v1.z; a1.w += v1.w;
        a2.x += v2.x; a2.y += v2.y; a2.z += v2.z; a2.w += v2.w;
        a3.x += v3.x; a3.y += v3.y; a3.z += v3.z; a3.w += v3.w;
    }
    for (; i < e; i++) {
        int c = g_col[i];
        float4 v = *(const float4*)&in[(size_t)c * 128 + lane * 4];
        a0.x += v.x; a0.y += v.y; a0.z += v.z; a0.w += v.w;
    }
    float inv = g_invdeg[n];
    r.x = (a0.x + a1.x + a2.x + a3.x) * inv;
    r.y = (a0.y + a1.y + a2.y + a3.y) * inv;
    r.z = (a0.z + a1.z + a2.z + a3.z) * inv;
    r.w = (a0.w + a1.w + a2.w + a3.w) * inv;
}

__global__ void k_agg(const float* __restrict__ in, float* __restrict__ out, int relu) {
    int n = blockIdx.x * 8 + (threadIdx.x >> 5);
    if (n >= N_NODES) return;
    int lane = threadIdx.x & 31;
    float4 r;
    agg_node(in, n, lane, r);
    if (relu) {
        r.x = fmaxf(r.x, 0.f); r.y = fmaxf(r.y, 0.f);
        r.z = fmaxf(r.z, 0.f); r.w = fmaxf(r.w, 0.f);
    }
    *(float4*)&out[(size_t)n * 128 + lane * 4] = r;
}

// target-chain first agg, restricted to in-neighbors of target nodes
__global__ void k_agg_tflagged(const float* __restrict__ in, float* __restrict__ out) {
    int n = blockIdx.x * 8 + (threadIdx.x >> 5);
    if (n >= N_NODES) return;
    if (!g_tflag[n]) return;
    int lane = threadIdx.x & 31;
    float4 r;
    agg_node(in, n, lane, r);
    r.x = fmaxf(r.x, 0.f); r.y = fmaxf(r.y, 0.f);
    r.z = fmaxf(r.z, 0.f); r.w = fmaxf(r.w, 0.f);
    *(float4*)&out[(size_t)n * 128 + lane * 4] = r;
}

__global__ void k_agg_flagged(const float* __restrict__ in, float* __restrict__ out) {
    int n = blockIdx.x * 8 + (threadIdx.x >> 5);
    if (n >= N_NODES) return;
    if (!g_flag[n]) return;
    int lane = threadIdx.x & 31;
    float4 r;
    agg_node(in, n, lane, r);
    *(float4*)&out[(size_t)n * 128 + lane * 4] = r;
}

__global__ void k_agg_target(const float* __restrict__ in, const int* __restrict__ tgt,
                             float* __restrict__ out) {
    int b = blockIdx.x * 8 + (threadIdx.x >> 5);
    if (b >= T_NODES) return;
    int lane = threadIdx.x & 31;
    int n = tgt[b];
    float4 r;
    agg_node(in, n, lane, r);
    *(float4*)&out[(size_t)b * 128 + lane * 4] = r;
}

// ---------------- fused predictor (tf32 MMA + ldmatrix, both layers) ---------------
// stage 1: hid[64,256] = relu(feats[64,136] @ W + zb)
// stage 2: out[64,128] = (hid @ Wp2 + bp2) * mask
// Weights staged TRANSPOSED [n][k_local] stride 36 (validated GEMM-B layout).
// A-fragments via ldmatrix on feats (stride 140) and hid (stride 260) — both
// conflict-free phase patterns.
#define FS_STR 140
#define WT_STR 36
#define HID_STR 260
// dynamic smem union (uints):
//   stage 1: [0 .. 64*FS_STR) feats (8960), [8960 .. +256*WT_STR) ws_t (9216)
//   stage 2: [0 .. 64*HID_STR) hid (16640), [16640 .. +128*WT_STR) ws2_t (4608)
#define PRED_SMEM_UINTS (64 * HID_STR + 128 * WT_STR)
#define PRED_SMEM (PRED_SMEM_UINTS * 4)

__global__ void __launch_bounds__(256)
k_pred(const float* __restrict__ m, const int* __restrict__ pair_s,
       const int* __restrict__ pair_t, const int* __restrict__ tgt,
       const float* __restrict__ mask, const float* __restrict__ Wp1,
       const float* __restrict__ Wp2, const float* __restrict__ bp2,
       float* __restrict__ out) {
    extern __shared__ unsigned sm[];
    int r0 = blockIdx.x * 64;
    int tid = threadIdx.x;
    __shared__ float ms[64];
    if (tid < 64) ms[tid] = mask[r0 + tid];
    int any = __syncthreads_or(tid < 64 && mask[r0 + tid] != 0.f);
    if (!any) {
        float4 zero = make_float4(0.f, 0.f, 0.f, 0.f);
#pragma unroll
        for (int i = 0; i < 8; i++) {
            int idx = tid + i * 256;
            *(float4*)&out[(size_t)r0 * 128 + idx * 4] = zero;
        }
        return;
    }

    unsigned* feats = sm;                   // stage 1 only
    unsigned* wst   = sm + 64 * FS_STR;     // stage 1 weights, transposed [n][k]
    unsigned* hid   = sm;                   // stage 2 (overwrites stage-1 region)
    unsigned* ws2t  = sm + 64 * HID_STR;    // stage 2 weights, transposed [n][k]

    int lane = tid & 31, wid = tid >> 5;
    int wm = wid & 1, wn = wid >> 1;
    int gid = lane >> 2, tig = lane & 3;

    // ldmatrix fragment base pointers
    const unsigned* pfa = &feats[(wm * 32 + (lane & 15)) * FS_STR + ((lane >> 4) << 2)];
    const unsigned* pwb = &wst[(wn * 64 + ((lane >> 4) << 3) + (lane & 7)) * WT_STR +
                               (((lane >> 3) & 1) << 2)];
    const unsigned* pha = &hid[(wm * 32 + (lane & 15)) * HID_STR + ((lane >> 4) << 2)];
    const unsigned* pw2b = &ws2t[(wn * 32 + ((lane >> 4) << 3) + (lane & 7)) * WT_STR +
                                 (((lane >> 3) & 1) << 2)];

    // ---------- stage 1: feats staging ----------
#pragma unroll
    for (int i = 0; i < 8; i++) {
        int idx = tid + i * 256;
        int r = idx >> 5, q = (idx & 31) << 2;
        int sN = pair_s[r0 + r];
        float4 v = *(const float4*)&m[(size_t)sN * 128 + q];
        uint4 u = make_uint4(f2tf(v.x), f2tf(v.y), f2tf(v.z), f2tf(v.w));
        *(uint4*)&feats[r * FS_STR + q] = u;
    }
    if (tid < 64) {
        int sN = pair_s[r0 + tid];
        int tN = tgt[pair_t[r0 + tid]];
        float4 ps = *(const float4*)&g_pe[sN * 4];
        float4 pt = *(const float4*)&g_pe[tN * 4];
        *(uint4*)&feats[tid * FS_STR + 128] =
            make_uint4(f2tf(ps.x), f2tf(ps.y), f2tf(ps.z), f2tf(ps.w));
        *(uint4*)&feats[tid * FS_STR + 132] =
            make_uint4(f2tf(pt.x), f2tf(pt.y), f2tf(pt.z), f2tf(pt.w));
    }

    float c[2][8][4];
#pragma unroll
    for (int mt = 0; mt < 2; mt++)
#pragma unroll
        for (int nt = 0; nt < 8; nt++)
#pragma unroll
            for (int q = 0; q < 4; q++) c[mt][nt][q] = 0.f;

    // 5 chunks: 4 x 32 k-rows from g_wf, then 8 k-rows from Wp1[192..200)
    for (int ch = 0; ch < 5; ch++) {
        int nrows = (ch < 4) ? 32 : 8;
        {
            // transposed weight staging: thread handles n = tid, all k-rows of chunk
            int n = tid;
            int nq = nrows >> 2;
#pragma unroll
            for (int q = 0; q < 8; q++) {
                if (q >= nq) break;
                int kk = q * 4;
                uint4 u;
                if (ch < 4) {
                    const float* base = &g_wf[(size_t)(ch * 32 + kk) * 256 + n];
                    u.x = f2tf(base[0]);
                    u.y = f2tf(base[256]);
                    u.z = f2tf(base[512]);
                    u.w = f2tf(base[768]);
                } else {
                    const float* base = &Wp1[(size_t)(192 + kk) * 256 + n];
                    u.x = f2tf(base[0]);
                    u.y = f2tf(base[256]);
                    u.z = f2tf(base[512]);
                    u.w = f2tf(base[768]);
                }
                *(uint4*)&wst[n * WT_STR + kk] = u;
            }
        }
        __syncthreads();
        int nks = nrows >> 3;
        for (int ks = 0; ks < nks; ks++) {
            int kb = ch * 32 + ks * 8;  // absolute k into feats
            int kl = ks * 8;            // local k into wst
            unsigned a[2][4], b[8][2];
            ldsm4(a[0], pfa + kb);
            ldsm4(a[1], pfa + 16 * FS_STR + kb);
#pragma unroll
            for (int p = 0; p < 4; p++) {
                unsigned t4[4];
                ldsm4(t4, pwb + p * 16 * WT_STR + kl);
                b[2 * p][0] = t4[0]; b[2 * p][1] = t4[1];
                b[2 * p + 1][0] = t4[2]; b[2 * p + 1][1] = t4[3];
            }
#pragma unroll
            for (int mt = 0; mt < 2; mt++)
#pragma unroll
                for (int nt = 0; nt < 8; nt++) mma8(c[mt][nt], a[mt], b[nt]);
        }
        __syncthreads();
    }

    // ---------- hidden -> smem (relu + zb, tf32) ----------
#pragma unroll
    for (int mt = 0; mt < 2; mt++) {
        int r = wm * 32 + mt * 16 + gid;
#pragma unroll
        for (int nt = 0; nt < 8; nt++) {
            int col = wn * 64 + nt * 8 + 2 * tig;
            float2 zbv = *(const float2*)&g_zb[col];
            uint2 u0 = make_uint2(f2tf(fmaxf(c[mt][nt][0] + zbv.x, 0.f)),
                                  f2tf(fmaxf(c[mt][nt][1] + zbv.y, 0.f)));
            uint2 u1 = make_uint2(f2tf(fmaxf(c[mt][nt][2] + zbv.x, 0.f)),
                                  f2tf(fmaxf(c[mt][nt][3] + zbv.y, 0.f)));
            *(uint2*)&hid[r * HID_STR + col] = u0;
            *(uint2*)&hid[(r + 8) * HID_STR + col] = u1;
        }
    }
    __syncthreads();

    // ---------- stage 2: hid @ Wp2, k=32 chunks ----------
    float c2[2][4][4];
#pragma unroll
    for (int mt = 0; mt < 2; mt++)
#pragma unroll
        for (int nt = 0; nt < 4; nt++)
#pragma unroll
            for (int q = 0; q < 4; q++) c2[mt][nt][q] = 0.f;

    int w2n = tid & 127, w2kh = (tid >> 7) * 16;
    for (int ch = 0; ch < 8; ch++) {
        {
            // transposed weight staging: [n][k_local], n = tid&127, 16 k per thread
#pragma unroll
            for (int q = 0; q < 4; q++) {
                int kk = w2kh + q * 4;
                const float* base = &Wp2[(size_t)(ch * 32 + kk) * 128 + w2n];
                uint4 u;
                u.x = f2tf(base[0]);
                u.y = f2tf(base[128]);
                u.z = f2tf(base[256]);
                u.w = f2tf(base[384]);
                *(uint4*)&ws2t[w2n * WT_STR + kk] = u;
            }
        }
        __syncthreads();
#pragma unroll
        for (int ks = 0; ks < 4; ks++) {
            int kb = ch * 32 + ks * 8;  // absolute k into hid
            int kl = ks * 8;            // local k into ws2t
            unsigned a[2][4], b[4][2];
            ldsm4(a[0], pha + kb);
            ldsm4(a[1], pha + 16 * HID_STR + kb);
#pragma unroll
            for (int p = 0; p < 2; p++) {
                unsigned t4[4];
                ldsm4(t4, pw2b + p * 16 * WT_STR + kl);
                b[2 * p][0] = t4[0]; b[2 * p][1] = t4[1];
                b[2 * p + 1][0] = t4[2]; b[2 * p + 1][1] = t4[3];
            }
#pragma unroll
            for (int mt = 0; mt < 2; mt++)
#pragma unroll
                for (int nt = 0; nt < 4; nt++) mma8(c2[mt][nt], a[mt], b[nt]);
        }
        __syncthreads();
    }

#pragma unroll
    for (int mt = 0; mt < 2; mt++) {
        int lr = wm * 32 + mt * 16 + gid;
        float m0v = ms[lr], m1v = ms[lr + 8];
#pragma unroll
        for (int nt = 0; nt < 4; nt++) {
            int col = wn * 32 + nt * 8 + 2 * tig;
            float2 bb = *(const float2*)&bp2[col];
            float2 v0 = make_float2((c2[mt][nt][0] + bb.x) * m0v,
                                    (c2[mt][nt][1] + bb.y) * m0v);
            float2 v1 = make_float2((c2[mt][nt][2] + bb.x) * m1v,
                                    (c2[mt][nt][3] + bb.y) * m1v);
            *(float2*)&out[(size_t)(r0 + lr) * 128 + col] = v0;
            *(float2*)&out[(size_t)(r0 + lr + 8) * 128 + col] = v1;
        }
    }
}

// ---------------- launch ----------------
extern "C" void kernel_launch(void* const* d_in, const int* in_sizes, int n_in,
                              void* d_out, int out_size) {
    const float* x            = (const float*)d_in[0];
    const float* masked_x     = (const float*)d_in[1];
    const float* pos_enc      = (const float*)d_in[2];
    const int*   edge_src     = (const int*)d_in[3];
    const int*   edge_dst     = (const int*)d_in[4];
    const int*   target_nodes = (const int*)d_in[5];
    const int*   pair_t       = (const int*)d_in[6];
    const int*   pair_s       = (const int*)d_in[7];
    const float* pair_mask    = (const float*)d_in[8];
    const float* W1t          = (const float*)d_in[9];
    const float* W2t          = (const float*)d_in[10];
    const float* W1c          = (const float*)d_in[11];
    const float* W2c          = (const float*)d_in[12];
    const float* Wpe          = (const float*)d_in[13];
    const float* z            = (const float*)d_in[14];
    const float* Wp1          = (const float*)d_in[15];
    const float* bp1          = (const float*)d_in[16];
    const float* Wp2          = (const float*)d_in[17];
    const float* bp2          = (const float*)d_in[18];
    float* out = (float*)d_out;

    float *buf1, *buf2, *tbuf;
    cudaGetSymbolAddress((void**)&buf1, g_buf1);
    cudaGetSymbolAddress((void**)&buf2, g_buf2);
    cudaGetSymbolAddress((void**)&tbuf, g_tbuf);

    cudaFuncSetAttribute(k_pred, cudaFuncAttributeMaxDynamicSharedMemorySize,
                         PRED_SMEM);

    const int TPB = 256;
    int gridN = (N_NODES + TPB - 1) / TPB;
    int gridE = (N_EDGES + TPB - 1) / TPB;
    int gridM = (N_NODES + 127) / 128;
    int gridA = (N_NODES + 7) / 8;

    // CSR build, big GEMM at launch slot 4 for the profiler window
    k_zero_cnt<<<gridN, TPB>>>();
    k_count<<<gridE, TPB>>>(edge_dst);
    k_scan<<<1, 1024>>>();
    k_gemm_tf32<<<gridM, 256>>>(x, W1t, buf2, N_NODES, 0);     // x @ W1t
    k_prep<<<gridN, TPB>>>();
    k_fill<<<gridE, TPB>>>(edge_src, edge_dst);
    k_flag<<<P_PAIRS / TPB, TPB>>>(pair_s, pair_mask);
    k_tflag<<<(T_NODES + TPB - 1) / TPB, TPB>>>(target_nodes);

    // tiny precomputes
    k_pe<<<gridN, TPB>>>(pos_enc, Wpe);
    k_zb<<<1, HP>>>(z, Wp1, bp1);
    k_wf<<<DIM, HP>>>(W2c, Wp1);

    // target GCN: h = relu(agg(xW1)) at tflag nodes only ; out_emb = agg(h)[targets] @ W2t
    k_agg_tflagged<<<gridA, 256>>>(buf2, buf1);
    k_agg_target<<<(T_NODES + 7) / 8, 256>>>(buf1, target_nodes, tbuf);
    k_gemm_tf32<<<T_NODES / 128, 256>>>(tbuf, W2t, out + (size_t)P_PAIRS * DOUT,
                                        T_NODES, 0);

    // context GCN: h_c = relu(agg(mxW1c)) ; m = agg(h_c) restricted to flagged nodes
    k_gemm_tf32<<<gridM, 256>>>(masked_x, W1c, buf2, N_NODES, 0);
    k_agg<<<gridA, 256>>>(buf2, buf1, 1);
    k_agg_flagged<<<gridA, 256>>>(buf1, buf2);   // m -> buf2

    // fused predictor MLP (64-row tiles, mask-tile skipping, ldmatrix fragments)
    k_pred<<<P_PAIRS / 64, 256, PRED_SMEM>>>(buf2, pair_s, pair_t, target_nodes,
                                             pair_mask, Wp1, Wp2, bp2, out);
}

// round 13
// speedup vs baseline: 1.0473x; 1.0473x over previous
#include <cuda_runtime.h>
#include <cuda_bf16.h>
#include <cstdint>

#define N_NODES 100000
#define N_EDGES 1600000
#define DIM     128
#define T_NODES 4096
#define P_PAIRS 131072
#define HP      256
#define DOUT    128
#define ZDIM    64

// ---------------- scratch (static device globals; no allocation) ----------------
__device__ int   g_cnt[N_NODES];
__device__ int   g_rowptr[N_NODES + 1];
__device__ int   g_cursor[N_NODES];
__device__ int   g_col[N_EDGES];
__device__ float g_invdeg[N_NODES];
__device__ unsigned char g_flag[N_NODES];
__device__ unsigned char g_tflag[N_NODES];
__device__ float g_pe[N_NODES * 4];
__device__ float g_zb[HP];
__device__ float g_wf[DIM * HP];                    // W2c @ Wp1[0:128]
__device__ float g_buf1[(size_t)N_NODES * DIM];
__device__ float g_buf2[(size_t)N_NODES * DIM];
__device__ float g_tbuf[(size_t)T_NODES * DIM];

// ---------------- tf32 / mma / bf16 helpers ----------------
__device__ __forceinline__ unsigned f2tf(float f) {
    unsigned u;
    asm("cvt.rna.tf32.f32 %0, %1;" : "=r"(u) : "f"(f));
    return u;
}
__device__ __forceinline__ void mma8(float* c, const unsigned* a, const unsigned* b) {
    asm volatile(
        "mma.sync.aligned.m16n8k8.row.col.f32.tf32.tf32.f32 "
        "{%0,%1,%2,%3},{%4,%5,%6,%7},{%8,%9},{%0,%1,%2,%3};"
        : "+f"(c[0]), "+f"(c[1]), "+f"(c[2]), "+f"(c[3])
        : "r"(a[0]), "r"(a[1]), "r"(a[2]), "r"(a[3]), "r"(b[0]), "r"(b[1]));
}
__device__ __forceinline__ void ldsm4(unsigned* r, const unsigned* p) {
    unsigned addr = (unsigned)__cvta_generic_to_shared(p);
    asm volatile("ldmatrix.sync.aligned.m8n8.x4.shared.b16 {%0,%1,%2,%3}, [%4];"
                 : "=r"(r[0]), "=r"(r[1]), "=r"(r[2]), "=r"(r[3]) : "r"(addr));
}
__device__ __forceinline__ float4 bf4_load(const __nv_bfloat16* p) {
    uint2 u = *(const uint2*)p;
    __nv_bfloat162 a = *reinterpret_cast<const __nv_bfloat162*>(&u.x);
    __nv_bfloat162 b = *reinterpret_cast<const __nv_bfloat162*>(&u.y);
    float2 fa = __bfloat1622float2(a), fb = __bfloat1622float2(b);
    return make_float4(fa.x, fa.y, fb.x, fb.y);
}
__device__ __forceinline__ void bf4_store(__nv_bfloat16* p, float4 v) {
    __nv_bfloat162 a = __float22bfloat162_rn(make_float2(v.x, v.y));
    __nv_bfloat162 b = __float22bfloat162_rn(make_float2(v.z, v.w));
    uint2 u;
    u.x = *reinterpret_cast<unsigned*>(&a);
    u.y = *reinterpret_cast<unsigned*>(&b);
    *(uint2*)p = u;
}

// ---------------- CSR build ----------------
__global__ void k_zero_cnt() {
    int i = blockIdx.x * blockDim.x + threadIdx.x;
    if (i < N_NODES) { g_cnt[i] = 0; g_flag[i] = 0; g_tflag[i] = 0; }
}

__global__ void k_count(const int* __restrict__ dst) {
    int e = blockIdx.x * blockDim.x + threadIdx.x;
    if (e < N_EDGES) atomicAdd(&g_cnt[dst[e]], 1);
}

__global__ void k_scan() {
    __shared__ int sums[1024];
    const int CH = (N_NODES + 1024) / 1024;
    int t = threadIdx.x;
    int base = t * CH;
    int s = 0;
    for (int i = 0; i < CH; i++) {
        int idx = base + i;
        if (idx < N_NODES) s += g_cnt[idx];
    }
    sums[t] = s;
    __syncthreads();
    for (int off = 1; off < 1024; off <<= 1) {
        int v = (t >= off) ? sums[t - off] : 0;
        __syncthreads();
        sums[t] += v;
        __syncthreads();
    }
    int run = sums[t] - s;
    for (int i = 0; i < CH; i++) {
        int idx = base + i;
        if (idx <= N_NODES) g_rowptr[idx] = run;
        if (idx < N_NODES) run += g_cnt[idx];
    }
}

__global__ void k_prep() {
    int i = blockIdx.x * blockDim.x + threadIdx.x;
    if (i < N_NODES) {
        g_cursor[i] = g_rowptr[i];
        int c = g_cnt[i];
        g_invdeg[i] = 1.0f / (float)(c > 0 ? c : 1);
    }
}

__global__ void k_fill(const int* __restrict__ src, const int* __restrict__ dst) {
    int e = blockIdx.x * blockDim.x + threadIdx.x;
    if (e < N_EDGES) {
        int pos = atomicAdd(&g_cursor[dst[e]], 1);
        g_col[pos] = src[e];
    }
}

__global__ void k_flag(const int* __restrict__ pair_s, const float* __restrict__ mask) {
    int i = blockIdx.x * blockDim.x + threadIdx.x;
    if (i < P_PAIRS && mask[i] != 0.f) g_flag[pair_s[i]] = 1;
}

// mark in-neighbors of target nodes (rows of h_t actually consumed by agg_target)
__global__ void k_tflag(const int* __restrict__ tgt) {
    int b = blockIdx.x * blockDim.x + threadIdx.x;
    if (b >= T_NODES) return;
    int n = tgt[b];
    int e = g_rowptr[n + 1];
    for (int i = g_rowptr[n]; i < e; i++) g_tflag[g_col[i]] = 1;
}

// ---------------- tiny precomputes ----------------
__global__ void k_pe(const float* __restrict__ pos_enc, const float* __restrict__ Wpe) {
    int n = blockIdx.x * blockDim.x + threadIdx.x;
    if (n >= N_NODES) return;
    float4 p = *(const float4*)&pos_enc[n * 4];
#pragma unroll
    for (int i = 0; i < 4; i++) {
        g_pe[n * 4 + i] = p.x * Wpe[i * 4 + 0] + p.y * Wpe[i * 4 + 1] +
                          p.z * Wpe[i * 4 + 2] + p.w * Wpe[i * 4 + 3];
    }
}

__global__ void k_zb(const float* __restrict__ z, const float* __restrict__ Wp1,
                     const float* __restrict__ bp1) {
    int j = threadIdx.x;
    float acc = bp1[j];
    for (int i = 0; i < ZDIM; i++) acc = fmaf(z[i], Wp1[(128 + i) * HP + j], acc);
    g_zb[j] = acc;
}

__global__ void k_wf(const float* __restrict__ W2c, const float* __restrict__ Wp1) {
    int i = blockIdx.x;
    int j = threadIdx.x;
    float acc = 0.f;
    for (int d = 0; d < DIM; d++) acc = fmaf(W2c[i * DIM + d], Wp1[d * HP + j], acc);
    g_wf[i * HP + j] = acc;
}

// ---------------- tf32 GEMM (R10-proven, ldmatrix): C = (relu?)(A @ B) -------------
// out_bf16: write C as bf16 (row stride 128 elems) instead of fp32.
#define AS_STR 36
#define BT_STR 36
__global__ void __launch_bounds__(256)
k_gemm_tf32(const float* __restrict__ A, const float* __restrict__ B,
            float* __restrict__ C, int M, int relu, int out_bf16) {
    __shared__ unsigned As[128 * AS_STR];
    __shared__ unsigned Bst[128 * BT_STR];
    int m0 = blockIdx.x * 128;
    int tid = threadIdx.x;
    int lane = tid & 31, wid = tid >> 5;
    int wm = wid & 3, wn = wid >> 2;      // rows wm*32, cols wn*64
    int gid = lane >> 2, tig = lane & 3;

    float c[2][8][4];
#pragma unroll
    for (int mt = 0; mt < 2; mt++)
#pragma unroll
        for (int nt = 0; nt < 8; nt++)
#pragma unroll
            for (int q = 0; q < 4; q++) c[mt][nt][q] = 0.f;

    int ar = tid >> 1, acb = (tid & 1) * 16;   // A stage: 128 rows x 32 k
    int bn = tid & 127, bkh = (tid >> 7) * 16; // B stage: 128 n x 32 k (transposed)

    const unsigned* pa0 = &As[(wm * 32 + (lane & 15)) * AS_STR + ((lane >> 4) << 2)];
    const unsigned* pa1 = pa0 + 16 * AS_STR;
    const unsigned* pb  = &Bst[(wn * 64 + ((lane >> 4) << 3) + (lane & 7)) * BT_STR +
                               (((lane >> 3) & 1) << 2)];

    for (int kc = 0; kc < 128; kc += 32) {
        {
            int grow = m0 + ar;
#pragma unroll
            for (int q = 0; q < 2; q++) {
                float4 v0 = (grow < M)
                    ? *(const float4*)&A[(size_t)grow * 128 + kc + acb + q * 8]
                    : make_float4(0.f, 0.f, 0.f, 0.f);
                float4 v1 = (grow < M)
                    ? *(const float4*)&A[(size_t)grow * 128 + kc + acb + q * 8 + 4]
                    : make_float4(0.f, 0.f, 0.f, 0.f);
                *(uint4*)&As[ar * AS_STR + acb + q * 8] =
                    make_uint4(f2tf(v0.x), f2tf(v0.y), f2tf(v0.z), f2tf(v0.w));
                *(uint4*)&As[ar * AS_STR + acb + q * 8 + 4] =
                    make_uint4(f2tf(v1.x), f2tf(v1.y), f2tf(v1.z), f2tf(v1.w));
            }
#pragma unroll
            for (int q = 0; q < 4; q++) {
                int kk = bkh + q * 4;
                uint4 u;
                u.x = f2tf(B[(size_t)(kc + kk + 0) * 128 + bn]);
                u.y = f2tf(B[(size_t)(kc + kk + 1) * 128 + bn]);
                u.z = f2tf(B[(size_t)(kc + kk + 2) * 128 + bn]);
                u.w = f2tf(B[(size_t)(kc + kk + 3) * 128 + bn]);
                *(uint4*)&Bst[bn * BT_STR + kk] = u;
            }
        }
        __syncthreads();
#pragma unroll
        for (int ks = 0; ks < 4; ks++) {
            int kb = ks * 8;
            unsigned a[2][4], b[8][2];
            ldsm4(a[0], pa0 + kb);
            ldsm4(a[1], pa1 + kb);
#pragma unroll
            for (int p = 0; p < 4; p++) {
                unsigned t4[4];
                ldsm4(t4, pb + p * 16 * BT_STR + kb);
                b[2 * p][0] = t4[0]; b[2 * p][1] = t4[1];
                b[2 * p + 1][0] = t4[2]; b[2 * p + 1][1] = t4[3];
            }
#pragma unroll
            for (int mt = 0; mt < 2; mt++)
#pragma unroll
                for (int nt = 0; nt < 8; nt++) mma8(c[mt][nt], a[mt], b[nt]);
        }
        __syncthreads();
    }

    __nv_bfloat16* Cb = (__nv_bfloat16*)C;
#pragma unroll
    for (int mt = 0; mt < 2; mt++) {
        int r = m0 + wm * 32 + mt * 16 + gid;
#pragma unroll
        for (int nt = 0; nt < 8; nt++) {
            int col = wn * 64 + nt * 8 + 2 * tig;
            float2 v0 = make_float2(c[mt][nt][0], c[mt][nt][1]);
            float2 v1 = make_float2(c[mt][nt][2], c[mt][nt][3]);
            if (relu) {
                v0.x = fmaxf(v0.x, 0.f); v0.y = fmaxf(v0.y, 0.f);
                v1.x = fmaxf(v1.x, 0.f); v1.y = fmaxf(v1.y, 0.f);
            }
            if (out_bf16) {
                __nv_bfloat162 b0 = __float22bfloat162_rn(v0);
                __nv_bfloat162 b1 = __float22bfloat162_rn(v1);
                if (r < M)     *(__nv_bfloat162*)&Cb[(size_t)r * 128 + col] = b0;
                if (r + 8 < M) *(__nv_bfloat162*)&Cb[(size_t)(r + 8) * 128 + col] = b1;
            } else {
                if (r < M)     *(float2*)&C[(size_t)r * 128 + col] = v0;
                if (r + 8 < M) *(float2*)&C[(size_t)(r + 8) * 128 + col] = v1;
            }
        }
    }
}

// ---------------- CSR gather-aggregation ----------------
__device__ __forceinline__ void agg_node(const float* __restrict__ in, int n, int lane,
                                         float4& r) {
    int s = g_rowptr[n], e = g_rowptr[n + 1];
    float4 a0 = make_float4(0.f, 0.f, 0.f, 0.f), a1 = a0, a2 = a0, a3 = a0;
    int i = s;
    for (; i + 4 <= e; i += 4) {
        int c0 = g_col[i], c1 = g_col[i + 1], c2 = g_col[i + 2], c3 = g_col[i + 3];
        float4 v0 = *(const float4*)&in[(size_t)c0 * 128 + lane * 4];
        float4 v1 = *(const float4*)&in[(size_t)c1 * 128 + lane * 4];
        float4 v2 = *(const float4*)&in[(size_t)c2 * 128 + lane * 4];
        float4 v3 = *(const float4*)&in[(size_t)c3 * 128 + lane * 4];
        a0.x += v0.x; a0.y += v0.y; a0.z += v0.z; a0.w += v0.w;
        a1.x += v1.x; a1.y += v1.y; a1.z += v1.z; a1.w += v1.w;
        a2.x += v2.x; a2.y += v2.y; a2.z += v2.z; a2.w += v2.w;
        a3.x += v3.x; a3.y += v3.y; a3.z += v3.z; a3.w += v3.w;
    }
    for (; i < e; i++) {
        int c = g_col[i];
        float4 v = *(const float4*)&in[(size_t)c * 128 + lane * 4];
        a0.x += v.x; a0.y += v.y; a0.z += v.z; a0.w += v.w;
    }
    float inv = g_invdeg[n];
    r.x = (a0.x + a1.x + a2.x + a3.x) * inv;
    r.y = (a0.y + a1.y + a2.y + a3.y) * inv;
    r.z = (a0.z + a1.z + a2.z + a3.z) * inv;
    r.w = (a0.w + a1.w + a2.w + a3.w) * inv;
}

// bf16-input variant (half the gather bytes); fp32 accumulation
__device__ __forceinline__ void agg_node_bf16(const __nv_bfloat16* __restrict__ in,
                                              int n, int lane, float4& r) {
    int s = g_rowptr[n], e = g_rowptr[n + 1];
    float4 a0 = make_float4(0.f, 0.f, 0.f, 0.f), a1 = a0, a2 = a0, a3 = a0;
    int i = s;
    for (; i + 4 <= e; i += 4) {
        int c0 = g_col[i], c1 = g_col[i + 1], c2 = g_col[i + 2], c3 = g_col[i + 3];
        float4 v0 = bf4_load(&in[(size_t)c0 * 128 + lane * 4]);
        float4 v1 = bf4_load(&in[(size_t)c1 * 128 + lane * 4]);
        float4 v2 = bf4_load(&in[(size_t)c2 * 128 + lane * 4]);
        float4 v3 = bf4_load(&in[(size_t)c3 * 128 + lane * 4]);
        a0.x += v0.x; a0.y += v0.y; a0.z += v0.z; a0.w += v0.w;
        a1.x += v1.x; a1.y += v1.y; a1.z += v1.z; a1.w += v1.w;
        a2.x += v2.x; a2.y += v2.y; a2.z += v2.z; a2.w += v2.w;
        a3.x += v3.x; a3.y += v3.y; a3.z += v3.z; a3.w += v3.w;
    }
    for (; i < e; i++) {
        int c = g_col[i];
        float4 v = bf4_load(&in[(size_t)c * 128 + lane * 4]);
        a0.x += v.x; a0.y += v.y; a0.z += v.z; a0.w += v.w;
    }
    float inv = g_invdeg[n];
    r.x = (a0.x + a1.x + a2.x + a3.x) * inv;
    r.y = (a0.y + a1.y + a2.y + a3.y) * inv;
    r.z = (a0.z + a1.z + a2.z + a3.z) * inv;
    r.w = (a0.w + a1.w + a2.w + a3.w) * inv;
}

// full agg: bf16 in -> relu -> bf16 out (context chain h_c)
__global__ void k_agg_b2b(const __nv_bfloat16* __restrict__ in,
                          __nv_bfloat16* __restrict__ out) {
    int n = blockIdx.x * 8 + (threadIdx.x >> 5);
    if (n >= N_NODES) return;
    int lane = threadIdx.x & 31;
    float4 r;
    agg_node_bf16(in, n, lane, r);
    r.x = fmaxf(r.x, 0.f); r.y = fmaxf(r.y, 0.f);
    r.z = fmaxf(r.z, 0.f); r.w = fmaxf(r.w, 0.f);
    bf4_store(&out[(size_t)n * 128 + lane * 4], r);
}

// target-chain first agg: bf16 in -> relu -> fp32 out, tflag-restricted
__global__ void k_agg_tflagged_b(const __nv_bfloat16* __restrict__ in,
                                 float* __restrict__ out) {
    int n = blockIdx.x * 8 + (threadIdx.x >> 5);
    if (n >= N_NODES) return;
    if (!g_tflag[n]) return;
    int lane = threadIdx.x & 31;
    float4 r;
    agg_node_bf16(in, n, lane, r);
    r.x = fmaxf(r.x, 0.f); r.y = fmaxf(r.y, 0.f);
    r.z = fmaxf(r.z, 0.f); r.w = fmaxf(r.w, 0.f);
    *(float4*)&out[(size_t)n * 128 + lane * 4] = r;
}

// context-chain second agg: bf16 in -> fp32 out, flag-restricted
__global__ void k_agg_flagged_b(const __nv_bfloat16* __restrict__ in,
                                float* __restrict__ out) {
    int n = blockIdx.x * 8 + (threadIdx.x >> 5);
    if (n >= N_NODES) return;
    if (!g_flag[n]) return;
    int lane = threadIdx.x & 31;
    float4 r;
    agg_node_bf16(in, n, lane, r);
    *(float4*)&out[(size_t)n * 128 + lane * 4] = r;
}

__global__ void k_agg_target(const float* __restrict__ in, const int* __restrict__ tgt,
                             float* __restrict__ out) {
    int b = blockIdx.x * 8 + (threadIdx.x >> 5);
    if (b >= T_NODES) return;
    int lane = threadIdx.x & 31;
    int n = tgt[b];
    float4 r;
    agg_node(in, n, lane, r);
    *(float4*)&out[(size_t)b * 128 + lane * 4] = r;
}

// ---------------- fused predictor (tf32 MMA + ldmatrix, both layers) ---------------
#define FS_STR 140
#define WT_STR 36
#define HID_STR 260
#define PRED_SMEM_UINTS (64 * HID_STR + 128 * WT_STR)
#define PRED_SMEM (PRED_SMEM_UINTS * 4)

__global__ void __launch_bounds__(256)
k_pred(const float* __restrict__ m, const int* __restrict__ pair_s,
       const int* __restrict__ pair_t, const int* __restrict__ tgt,
       const float* __restrict__ mask, const float* __restrict__ Wp1,
       const float* __restrict__ Wp2, const float* __restrict__ bp2,
       float* __restrict__ out) {
    extern __shared__ unsigned sm[];
    int r0 = blockIdx.x * 64;
    int tid = threadIdx.x;
    __shared__ float ms[64];
    if (tid < 64) ms[tid] = mask[r0 + tid];
    int any = __syncthreads_or(tid < 64 && mask[r0 + tid] != 0.f);
    if (!any) {
        float4 zero = make_float4(0.f, 0.f, 0.f, 0.f);
#pragma unroll
        for (int i = 0; i < 8; i++) {
            int idx = tid + i * 256;
            *(float4*)&out[(size_t)r0 * 128 + idx * 4] = zero;
        }
        return;
    }

    unsigned* feats = sm;
    unsigned* wst   = sm + 64 * FS_STR;
    unsigned* hid   = sm;
    unsigned* ws2t  = sm + 64 * HID_STR;

    int lane = tid & 31, wid = tid >> 5;
    int wm = wid & 1, wn = wid >> 1;
    int gid = lane >> 2, tig = lane & 3;

    const unsigned* pfa = &feats[(wm * 32 + (lane & 15)) * FS_STR + ((lane >> 4) << 2)];
    const unsigned* pwb = &wst[(wn * 64 + ((lane >> 4) << 3) + (lane & 7)) * WT_STR +
                               (((lane >> 3) & 1) << 2)];
    const unsigned* pha = &hid[(wm * 32 + (lane & 15)) * HID_STR + ((lane >> 4) << 2)];
    const unsigned* pw2b = &ws2t[(wn * 32 + ((lane >> 4) << 3) + (lane & 7)) * WT_STR +
                                 (((lane >> 3) & 1) << 2)];

    // ---------- stage 1: feats staging ----------
#pragma unroll
    for (int i = 0; i < 8; i++) {
        int idx = tid + i * 256;
        int r = idx >> 5, q = (idx & 31) << 2;
        int sN = pair_s[r0 + r];
        float4 v = *(const float4*)&m[(size_t)sN * 128 + q];
        uint4 u = make_uint4(f2tf(v.x), f2tf(v.y), f2tf(v.z), f2tf(v.w));
        *(uint4*)&feats[r * FS_STR + q] = u;
    }
    if (tid < 64) {
        int sN = pair_s[r0 + tid];
        int tN = tgt[pair_t[r0 + tid]];
        float4 ps = *(const float4*)&g_pe[sN * 4];
        float4 pt = *(const float4*)&g_pe[tN * 4];
        *(uint4*)&feats[tid * FS_STR + 128] =
            make_uint4(f2tf(ps.x), f2tf(ps.y), f2tf(ps.z), f2tf(ps.w));
        *(uint4*)&feats[tid * FS_STR + 132] =
            make_uint4(f2tf(pt.x), f2tf(pt.y), f2tf(pt.z), f2tf(pt.w));
    }

    float c[2][8][4];
#pragma unroll
    for (int mt = 0; mt < 2; mt++)
#pragma unroll
        for (int nt = 0; nt < 8; nt++)
#pragma unroll
            for (int q = 0; q < 4; q++) c[mt][nt][q] = 0.f;

    for (int ch = 0; ch < 5; ch++) {
        int nrows = (ch < 4) ? 32 : 8;
        {
            int n = tid;
            int nq = nrows >> 2;
#pragma unroll
            for (int q = 0; q < 8; q++) {
                if (q >= nq) break;
                int kk = q * 4;
                uint4 u;
                if (ch < 4) {
                    const float* base = &g_wf[(size_t)(ch * 32 + kk) * 256 + n];
                    u.x = f2tf(base[0]);
                    u.y = f2tf(base[256]);
                    u.z = f2tf(base[512]);
                    u.w = f2tf(base[768]);
                } else {
                    const float* base = &Wp1[(size_t)(192 + kk) * 256 + n];
                    u.x = f2tf(base[0]);
                    u.y = f2tf(base[256]);
                    u.z = f2tf(base[512]);
                    u.w = f2tf(base[768]);
                }
                *(uint4*)&wst[n * WT_STR + kk] = u;
            }
        }
        __syncthreads();
        int nks = nrows >> 3;
        for (int ks = 0; ks < nks; ks++) {
            int kb = ch * 32 + ks * 8;
            int kl = ks * 8;
            unsigned a[2][4], b[8][2];
            ldsm4(a[0], pfa + kb);
            ldsm4(a[1], pfa + 16 * FS_STR + kb);
#pragma unroll
            for (int p = 0; p < 4; p++) {
                unsigned t4[4];
                ldsm4(t4, pwb + p * 16 * WT_STR + kl);
                b[2 * p][0] = t4[0]; b[2 * p][1] = t4[1];
                b[2 * p + 1][0] = t4[2]; b[2 * p + 1][1] = t4[3];
            }
#pragma unroll
            for (int mt = 0; mt < 2; mt++)
#pragma unroll
                for (int nt = 0; nt < 8; nt++) mma8(c[mt][nt], a[mt], b[nt]);
        }
        __syncthreads();
    }

    // ---------- hidden -> smem (relu + zb, tf32) ----------
#pragma unroll
    for (int mt = 0; mt < 2; mt++) {
        int r = wm * 32 + mt * 16 + gid;
#pragma unroll
        for (int nt = 0; nt < 8; nt++) {
            int col = wn * 64 + nt * 8 + 2 * tig;
            float2 zbv = *(const float2*)&g_zb[col];
            uint2 u0 = make_uint2(f2tf(fmaxf(c[mt][nt][0] + zbv.x, 0.f)),
                                  f2tf(fmaxf(c[mt][nt][1] + zbv.y, 0.f)));
            uint2 u1 = make_uint2(f2tf(fmaxf(c[mt][nt][2] + zbv.x, 0.f)),
                                  f2tf(fmaxf(c[mt][nt][3] + zbv.y, 0.f)));
            *(uint2*)&hid[r * HID_STR + col] = u0;
            *(uint2*)&hid[(r + 8) * HID_STR + col] = u1;
        }
    }
    __syncthreads();

    // ---------- stage 2: hid @ Wp2, k=32 chunks ----------
    float c2[2][4][4];
#pragma unroll
    for (int mt = 0; mt < 2; mt++)
#pragma unroll
        for (int nt = 0; nt < 4; nt++)
#pragma unroll
            for (int q = 0; q < 4; q++) c2[mt][nt][q] = 0.f;

    int w2n = tid & 127, w2kh = (tid >> 7) * 16;
    for (int ch = 0; ch < 8; ch++) {
        {
#pragma unroll
            for (int q = 0; q < 4; q++) {
                int kk = w2kh + q * 4;
                const float* base = &Wp2[(size_t)(ch * 32 + kk) * 128 + w2n];
                uint4 u;
                u.x = f2tf(base[0]);
                u.y = f2tf(base[128]);
                u.z = f2tf(base[256]);
                u.w = f2tf(base[384]);
                *(uint4*)&ws2t[w2n * WT_STR + kk] = u;
            }
        }
        __syncthreads();
#pragma unroll
        for (int ks = 0; ks < 4; ks++) {
            int kb = ch * 32 + ks * 8;
            int kl = ks * 8;
            unsigned a[2][4], b[4][2];
            ldsm4(a[0], pha + kb);
            ldsm4(a[1], pha + 16 * HID_STR + kb);
#pragma unroll
            for (int p = 0; p < 2; p++) {
                unsigned t4[4];
                ldsm4(t4, pw2b + p * 16 * WT_STR + kl);
                b[2 * p][0] = t4[0]; b[2 * p][1] = t4[1];
                b[2 * p + 1][0] = t4[2]; b[2 * p + 1][1] = t4[3];
            }
#pragma unroll
            for (int mt = 0; mt < 2; mt++)
#pragma unroll
                for (int nt = 0; nt < 4; nt++) mma8(c2[mt][nt], a[mt], b[nt]);
        }
        __syncthreads();
    }

#pragma unroll
    for (int mt = 0; mt < 2; mt++) {
        int lr = wm * 32 + mt * 16 + gid;
        float m0v = ms[lr], m1v = ms[lr + 8];
#pragma unroll
        for (int nt = 0; nt < 4; nt++) {
            int col = wn * 32 + nt * 8 + 2 * tig;
            float2 bb = *(const float2*)&bp2[col];
            float2 v0 = make_float2((c2[mt][nt][0] + bb.x) * m0v,
                                    (c2[mt][nt][1] + bb.y) * m0v);
            float2 v1 = make_float2((c2[mt][nt][2] + bb.x) * m1v,
                                    (c2[mt][nt][3] + bb.y) * m1v);
            *(float2*)&out[(size_t)(r0 + lr) * 128 + col] = v0;
            *(float2*)&out[(size_t)(r0 + lr + 8) * 128 + col] = v1;
        }
    }
}

// ---------------- launch ----------------
extern "C" void kernel_launch(void* const* d_in, const int* in_sizes, int n_in,
                              void* d_out, int out_size) {
    const float* x            = (const float*)d_in[0];
    const float* masked_x     = (const float*)d_in[1];
    const float* pos_enc      = (const float*)d_in[2];
    const int*   edge_src     = (const int*)d_in[3];
    const int*   edge_dst     = (const int*)d_in[4];
    const int*   target_nodes = (const int*)d_in[5];
    const int*   pair_t       = (const int*)d_in[6];
    const int*   pair_s       = (const int*)d_in[7];
    const float* pair_mask    = (const float*)d_in[8];
    const float* W1t          = (const float*)d_in[9];
    const float* W2t          = (const float*)d_in[10];
    const float* W1c          = (const float*)d_in[11];
    const float* W2c          = (const float*)d_in[12];
    const float* Wpe          = (const float*)d_in[13];
    const float* z            = (const float*)d_in[14];
    const float* Wp1          = (const float*)d_in[15];
    const float* bp1          = (const float*)d_in[16];
    const float* Wp2          = (const float*)d_in[17];
    const float* bp2          = (const float*)d_in[18];
    float* out = (float*)d_out;

    float *buf1, *buf2, *tbuf;
    cudaGetSymbolAddress((void**)&buf1, g_buf1);
    cudaGetSymbolAddress((void**)&buf2, g_buf2);
    cudaGetSymbolAddress((void**)&tbuf, g_tbuf);
    __nv_bfloat16* buf1b = (__nv_bfloat16*)buf1;
    __nv_bfloat16* buf2b = (__nv_bfloat16*)buf2;

    cudaFuncSetAttribute(k_pred, cudaFuncAttributeMaxDynamicSharedMemorySize,
                         PRED_SMEM);

    const int TPB = 256;
    int gridN = (N_NODES + TPB - 1) / TPB;
    int gridE = (N_EDGES + TPB - 1) / TPB;
    int gridM = (N_NODES + 127) / 128;
    int gridA = (N_NODES + 7) / 8;

    // CSR build, big GEMM at launch slot 4 for the profiler window
    k_zero_cnt<<<gridN, TPB>>>();
    k_count<<<gridE, TPB>>>(edge_dst);
    k_scan<<<1, 1024>>>();
    k_gemm_tf32<<<gridM, 256>>>(x, W1t, buf2, N_NODES, 0, 1);   // x @ W1t -> bf16
    k_prep<<<gridN, TPB>>>();
    k_fill<<<gridE, TPB>>>(edge_src, edge_dst);
    k_flag<<<P_PAIRS / TPB, TPB>>>(pair_s, pair_mask);
    k_tflag<<<(T_NODES + TPB - 1) / TPB, TPB>>>(target_nodes);

    // tiny precomputes
    k_pe<<<gridN, TPB>>>(pos_enc, Wpe);
    k_zb<<<1, HP>>>(z, Wp1, bp1);
    k_wf<<<DIM, HP>>>(W2c, Wp1);

    // target GCN: h = relu(agg(xW1)) at tflag nodes ; out_emb = agg(h)[targets] @ W2t
    k_agg_tflagged_b<<<gridA, 256>>>(buf2b, buf1);
    k_agg_target<<<(T_NODES + 7) / 8, 256>>>(buf1, target_nodes, tbuf);
    k_gemm_tf32<<<T_NODES / 128, 256>>>(tbuf, W2t, out + (size_t)P_PAIRS * DOUT,
                                        T_NODES, 0, 0);

    // context GCN: h_c = relu(agg(mxW1c)) (bf16) ; m = agg(h_c) at flagged nodes
    k_gemm_tf32<<<gridM, 256>>>(masked_x, W1c, buf1, N_NODES, 0, 1);  // -> bf16
    k_agg_b2b<<<gridA, 256>>>(buf1b, buf2b);        // h_c bf16 -> buf2 (bf16)
    k_agg_flagged_b<<<gridA, 256>>>(buf2b, buf1);   // m fp32 -> buf1

    // fused predictor MLP (64-row tiles, mask-tile skipping, ldmatrix fragments)
    k_pred<<<P_PAIRS / 64, 256, PRED_SMEM>>>(buf1, pair_s, pair_t, target_nodes,
                                             pair_mask, Wp1, Wp2, bp2, out);
}

// round 14
// speedup vs baseline: 1.0871x; 1.0380x over previous
#include <cuda_runtime.h>
#include <cuda_bf16.h>
#include <cstdint>

#define N_NODES 100000
#define N_EDGES 1600000
#define DIM     128
#define T_NODES 4096
#define P_PAIRS 131072
#define HP      256
#define DOUT    128
#define ZDIM    64

// ---------------- scratch (static device globals; no allocation) ----------------
__device__ int   g_cnt[N_NODES];
__device__ int   g_rowptr[N_NODES + 1];
__device__ int   g_cursor[N_NODES];
__device__ int   g_col[N_EDGES];
__device__ float g_invdeg[N_NODES];
__device__ unsigned char g_flag[N_NODES];
__device__ unsigned char g_tflag[N_NODES];
__device__ float g_pe[N_NODES * 4];
__device__ float g_zb[HP];
__device__ float g_wf[DIM * HP];                    // W2c @ Wp1[0:128]
__device__ float g_buf1[(size_t)N_NODES * DIM];    // gemm_t out (bf16) -> later m (fp32)
__device__ float g_buf2[(size_t)N_NODES * DIM];    // gemm_c out (bf16)
__device__ float g_buf3[(size_t)N_NODES * DIM];    // ht (fp32, tflag rows)
__device__ float g_buf4[(size_t)N_NODES * DIM];    // h_c (bf16)
__device__ float g_tbuf[(size_t)T_NODES * DIM];

// ---------------- tf32 / mma / bf16 helpers ----------------
__device__ __forceinline__ unsigned f2tf(float f) {
    unsigned u;
    asm("cvt.rna.tf32.f32 %0, %1;" : "=r"(u) : "f"(f));
    return u;
}
__device__ __forceinline__ void mma8(float* c, const unsigned* a, const unsigned* b) {
    asm volatile(
        "mma.sync.aligned.m16n8k8.row.col.f32.tf32.tf32.f32 "
        "{%0,%1,%2,%3},{%4,%5,%6,%7},{%8,%9},{%0,%1,%2,%3};"
        : "+f"(c[0]), "+f"(c[1]), "+f"(c[2]), "+f"(c[3])
        : "r"(a[0]), "r"(a[1]), "r"(a[2]), "r"(a[3]), "r"(b[0]), "r"(b[1]));
}
__device__ __forceinline__ void ldsm4(unsigned* r, const unsigned* p) {
    unsigned addr = (unsigned)__cvta_generic_to_shared(p);
    asm volatile("ldmatrix.sync.aligned.m8n8.x4.shared.b16 {%0,%1,%2,%3}, [%4];"
                 : "=r"(r[0]), "=r"(r[1]), "=r"(r[2]), "=r"(r[3]) : "r"(addr));
}
__device__ __forceinline__ float4 bf4_load(const __nv_bfloat16* p) {
    uint2 u = *(const uint2*)p;
    __nv_bfloat162 a = *reinterpret_cast<const __nv_bfloat162*>(&u.x);
    __nv_bfloat162 b = *reinterpret_cast<const __nv_bfloat162*>(&u.y);
    float2 fa = __bfloat1622float2(a), fb = __bfloat1622float2(b);
    return make_float4(fa.x, fa.y, fb.x, fb.y);
}
__device__ __forceinline__ void bf4_store(__nv_bfloat16* p, float4 v) {
    __nv_bfloat162 a = __float22bfloat162_rn(make_float2(v.x, v.y));
    __nv_bfloat162 b = __float22bfloat162_rn(make_float2(v.z, v.w));
    uint2 u;
    u.x = *reinterpret_cast<unsigned*>(&a);
    u.y = *reinterpret_cast<unsigned*>(&b);
    *(uint2*)p = u;
}

// ---------------- GEMM body (R10-proven, ldmatrix) ----------------
#define AS_STR 36
#define BT_STR 36
#define GM 782   // gemm grid for M = N_NODES

__device__ void gemm_body(int bid, const float* __restrict__ A,
                          const float* __restrict__ B, float* __restrict__ C,
                          int M, int relu, int out_bf16) {
    __shared__ unsigned As[128 * AS_STR];
    __shared__ unsigned Bst[128 * BT_STR];
    int m0 = bid * 128;
    int tid = threadIdx.x;
    int lane = tid & 31, wid = tid >> 5;
    int wm = wid & 3, wn = wid >> 2;
    int gid = lane >> 2, tig = lane & 3;

    float c[2][8][4];
#pragma unroll
    for (int mt = 0; mt < 2; mt++)
#pragma unroll
        for (int nt = 0; nt < 8; nt++)
#pragma unroll
            for (int q = 0; q < 4; q++) c[mt][nt][q] = 0.f;

    int ar = tid >> 1, acb = (tid & 1) * 16;
    int bn = tid & 127, bkh = (tid >> 7) * 16;

    const unsigned* pa0 = &As[(wm * 32 + (lane & 15)) * AS_STR + ((lane >> 4) << 2)];
    const unsigned* pa1 = pa0 + 16 * AS_STR;
    const unsigned* pb  = &Bst[(wn * 64 + ((lane >> 4) << 3) + (lane & 7)) * BT_STR +
                               (((lane >> 3) & 1) << 2)];

    for (int kc = 0; kc < 128; kc += 32) {
        {
            int grow = m0 + ar;
#pragma unroll
            for (int q = 0; q < 2; q++) {
                float4 v0 = (grow < M)
                    ? *(const float4*)&A[(size_t)grow * 128 + kc + acb + q * 8]
                    : make_float4(0.f, 0.f, 0.f, 0.f);
                float4 v1 = (grow < M)
                    ? *(const float4*)&A[(size_t)grow * 128 + kc + acb + q * 8 + 4]
                    : make_float4(0.f, 0.f, 0.f, 0.f);
                *(uint4*)&As[ar * AS_STR + acb + q * 8] =
                    make_uint4(f2tf(v0.x), f2tf(v0.y), f2tf(v0.z), f2tf(v0.w));
                *(uint4*)&As[ar * AS_STR + acb + q * 8 + 4] =
                    make_uint4(f2tf(v1.x), f2tf(v1.y), f2tf(v1.z), f2tf(v1.w));
            }
#pragma unroll
            for (int q = 0; q < 4; q++) {
                int kk = bkh + q * 4;
                uint4 u;
                u.x = f2tf(B[(size_t)(kc + kk + 0) * 128 + bn]);
                u.y = f2tf(B[(size_t)(kc + kk + 1) * 128 + bn]);
                u.z = f2tf(B[(size_t)(kc + kk + 2) * 128 + bn]);
                u.w = f2tf(B[(size_t)(kc + kk + 3) * 128 + bn]);
                *(uint4*)&Bst[bn * BT_STR + kk] = u;
            }
        }
        __syncthreads();
#pragma unroll
        for (int ks = 0; ks < 4; ks++) {
            int kb = ks * 8;
            unsigned a[2][4], b[8][2];
            ldsm4(a[0], pa0 + kb);
            ldsm4(a[1], pa1 + kb);
#pragma unroll
            for (int p = 0; p < 4; p++) {
                unsigned t4[4];
                ldsm4(t4, pb + p * 16 * BT_STR + kb);
                b[2 * p][0] = t4[0]; b[2 * p][1] = t4[1];
                b[2 * p + 1][0] = t4[2]; b[2 * p + 1][1] = t4[3];
            }
#pragma unroll
            for (int mt = 0; mt < 2; mt++)
#pragma unroll
                for (int nt = 0; nt < 8; nt++) mma8(c[mt][nt], a[mt], b[nt]);
        }
        __syncthreads();
    }

    __nv_bfloat16* Cb = (__nv_bfloat16*)C;
#pragma unroll
    for (int mt = 0; mt < 2; mt++) {
        int r = m0 + wm * 32 + mt * 16 + gid;
#pragma unroll
        for (int nt = 0; nt < 8; nt++) {
            int col = wn * 64 + nt * 8 + 2 * tig;
            float2 v0 = make_float2(c[mt][nt][0], c[mt][nt][1]);
            float2 v1 = make_float2(c[mt][nt][2], c[mt][nt][3]);
            if (relu) {
                v0.x = fmaxf(v0.x, 0.f); v0.y = fmaxf(v0.y, 0.f);
                v1.x = fmaxf(v1.x, 0.f); v1.y = fmaxf(v1.y, 0.f);
            }
            if (out_bf16) {
                __nv_bfloat162 b0 = __float22bfloat162_rn(v0);
                __nv_bfloat162 b1 = __float22bfloat162_rn(v1);
                if (r < M)     *(__nv_bfloat162*)&Cb[(size_t)r * 128 + col] = b0;
                if (r + 8 < M) *(__nv_bfloat162*)&Cb[(size_t)(r + 8) * 128 + col] = b1;
            } else {
                if (r < M)     *(float2*)&C[(size_t)r * 128 + col] = v0;
                if (r + 8 < M) *(float2*)&C[(size_t)(r + 8) * 128 + col] = v1;
            }
        }
    }
}

__global__ void __launch_bounds__(256)
k_gemm_tf32(const float* __restrict__ A, const float* __restrict__ B,
            float* __restrict__ C, int M, int relu, int out_bf16) {
    gemm_body(blockIdx.x, A, B, C, M, relu, out_bf16);
}

// ---------------- fused F1: gemm_t (x@W1t -> buf1 bf16) || zero arrays -------------
#define F1_CSR 256
__global__ void __launch_bounds__(256)
k_f1(const float* __restrict__ x, const float* __restrict__ W1t) {
    if (blockIdx.x < GM) {
        gemm_body(blockIdx.x, x, W1t, g_buf1, N_NODES, 0, 1);
        return;
    }
    int stride = F1_CSR * 256;
    for (int i = (blockIdx.x - GM) * 256 + threadIdx.x; i < N_NODES; i += stride) {
        g_cnt[i] = 0;
        g_flag[i] = 0;
        g_tflag[i] = 0;
    }
}

// ---------------- fused F2: gemm_c (mx@W1c -> buf2 bf16) || count ------------------
#define F2_CSR 512
__global__ void __launch_bounds__(256)
k_f2(const float* __restrict__ mx, const float* __restrict__ W1c,
     const int* __restrict__ dst) {
    if (blockIdx.x < GM) {
        gemm_body(blockIdx.x, mx, W1c, g_buf2, N_NODES, 0, 1);
        return;
    }
    int stride = F2_CSR * 256;
    for (int e = (blockIdx.x - GM) * 256 + threadIdx.x; e < N_EDGES; e += stride)
        atomicAdd(&g_cnt[dst[e]], 1);
}

// ---------------- scan / prep (standalone) ----------------
__global__ void k_scan() {
    __shared__ int sums[1024];
    const int CH = (N_NODES + 1024) / 1024;
    int t = threadIdx.x;
    int base = t * CH;
    int s = 0;
    for (int i = 0; i < CH; i++) {
        int idx = base + i;
        if (idx < N_NODES) s += g_cnt[idx];
    }
    sums[t] = s;
    __syncthreads();
    for (int off = 1; off < 1024; off <<= 1) {
        int v = (t >= off) ? sums[t - off] : 0;
        __syncthreads();
        sums[t] += v;
        __syncthreads();
    }
    int run = sums[t] - s;
    for (int i = 0; i < CH; i++) {
        int idx = base + i;
        if (idx <= N_NODES) g_rowptr[idx] = run;
        if (idx < N_NODES) run += g_cnt[idx];
    }
}

__global__ void k_prep() {
    int i = blockIdx.x * blockDim.x + threadIdx.x;
    if (i < N_NODES) {
        g_cursor[i] = g_rowptr[i];
        int c = g_cnt[i];
        g_invdeg[i] = 1.0f / (float)(c > 0 ? c : 1);
    }
}

// ---------------- fused F3: fill || pe || wf || zb || flag -------------------------
#define F3_FILL 1024
#define F3_PE   391
#define F3_WF   128
// layout: [0,1024) fill | [1024,1415) pe | [1415,1543) wf | [1543] zb | [1544,2056) flag
#define F3_GRID (F3_FILL + F3_PE + F3_WF + 1 + 512)
__global__ void __launch_bounds__(256)
k_f3(const int* __restrict__ src, const int* __restrict__ dst,
     const float* __restrict__ pos_enc, const float* __restrict__ Wpe,
     const float* __restrict__ W2c, const float* __restrict__ Wp1,
     const float* __restrict__ z, const float* __restrict__ bp1,
     const int* __restrict__ pair_s, const float* __restrict__ mask) {
    int b = blockIdx.x, tid = threadIdx.x;
    if (b < F3_FILL) {
        int stride = F3_FILL * 256;
        for (int e = b * 256 + tid; e < N_EDGES; e += stride) {
            int pos = atomicAdd(&g_cursor[dst[e]], 1);
            g_col[pos] = src[e];
        }
    } else if (b < F3_FILL + F3_PE) {
        int n = (b - F3_FILL) * 256 + tid;
        if (n < N_NODES) {
            float4 p = *(const float4*)&pos_enc[n * 4];
#pragma unroll
            for (int i = 0; i < 4; i++) {
                g_pe[n * 4 + i] = p.x * Wpe[i * 4 + 0] + p.y * Wpe[i * 4 + 1] +
                                  p.z * Wpe[i * 4 + 2] + p.w * Wpe[i * 4 + 3];
            }
        }
    } else if (b < F3_FILL + F3_PE + F3_WF) {
        int i = b - F3_FILL - F3_PE;
        int j = tid;
        float acc = 0.f;
        for (int d = 0; d < DIM; d++)
            acc = fmaf(W2c[i * DIM + d], Wp1[d * HP + j], acc);
        g_wf[i * HP + j] = acc;
    } else if (b < F3_FILL + F3_PE + F3_WF + 1) {
        int j = tid;
        float acc = bp1[j];
        for (int i = 0; i < ZDIM; i++)
            acc = fmaf(z[i], Wp1[(128 + i) * HP + j], acc);
        g_zb[j] = acc;
    } else {
        int i = (b - F3_FILL - F3_PE - F3_WF - 1) * 256 + tid;
        if (i < P_PAIRS && mask[i] != 0.f) g_flag[pair_s[i]] = 1;
    }
}

__global__ void k_tflag(const int* __restrict__ tgt) {
    int b = blockIdx.x * blockDim.x + threadIdx.x;
    if (b >= T_NODES) return;
    int n = tgt[b];
    int e = g_rowptr[n + 1];
    for (int i = g_rowptr[n]; i < e; i++) g_tflag[g_col[i]] = 1;
}

// ---------------- agg bodies ----------------
__device__ __forceinline__ void agg_node(const float* __restrict__ in, int n, int lane,
                                         float4& r) {
    int s = g_rowptr[n], e = g_rowptr[n + 1];
    float4 a0 = make_float4(0.f, 0.f, 0.f, 0.f), a1 = a0, a2 = a0, a3 = a0;
    int i = s;
    for (; i + 4 <= e; i += 4) {
        int c0 = g_col[i], c1 = g_col[i + 1], c2 = g_col[i + 2], c3 = g_col[i + 3];
        float4 v0 = *(const float4*)&in[(size_t)c0 * 128 + lane * 4];
        float4 v1 = *(const float4*)&in[(size_t)c1 * 128 + lane * 4];
        float4 v2 = *(const float4*)&in[(size_t)c2 * 128 + lane * 4];
        float4 v3 = *(const float4*)&in[(size_t)c3 * 128 + lane * 4];
        a0.x += v0.x; a0.y += v0.y; a0.z += v0.z; a0.w += v0.w;
        a1.x += v1.x; a1.y += v1.y; a1.z += v1.z; a1.w += v1.w;
        a2.x += v2.x; a2.y += v2.y; a2.z += v2.z; a2.w += v2.w;
        a3.x += v3.x; a3.y += v3.y; a3.z += v3.z; a3.w += v3.w;
    }
    for (; i < e; i++) {
        int c = g_col[i];
        float4 v = *(const float4*)&in[(size_t)c * 128 + lane * 4];
        a0.x += v.x; a0.y += v.y; a0.z += v.z; a0.w += v.w;
    }
    float inv = g_invdeg[n];
    r.x = (a0.x + a1.x + a2.x + a3.x) * inv;
    r.y = (a0.y + a1.y + a2.y + a3.y) * inv;
    r.z = (a0.z + a1.z + a2.z + a3.z) * inv;
    r.w = (a0.w + a1.w + a2.w + a3.w) * inv;
}

__device__ __forceinline__ void agg_node_bf16(const __nv_bfloat16* __restrict__ in,
                                              int n, int lane, float4& r) {
    int s = g_rowptr[n], e = g_rowptr[n + 1];
    float4 a0 = make_float4(0.f, 0.f, 0.f, 0.f), a1 = a0, a2 = a0, a3 = a0;
    int i = s;
    for (; i + 4 <= e; i += 4) {
        int c0 = g_col[i], c1 = g_col[i + 1], c2 = g_col[i + 2], c3 = g_col[i + 3];
        float4 v0 = bf4_load(&in[(size_t)c0 * 128 + lane * 4]);
        float4 v1 = bf4_load(&in[(size_t)c1 * 128 + lane * 4]);
        float4 v2 = bf4_load(&in[(size_t)c2 * 128 + lane * 4]);
        float4 v3 = bf4_load(&in[(size_t)c3 * 128 + lane * 4]);
        a0.x += v0.x; a0.y += v0.y; a0.z += v0.z; a0.w += v0.w;
        a1.x += v1.x; a1.y += v1.y; a1.z += v1.z; a1.w += v1.w;
        a2.x += v2.x; a2.y += v2.y; a2.z += v2.z; a2.w += v2.w;
        a3.x += v3.x; a3.y += v3.y; a3.z += v3.z; a3.w += v3.w;
    }
    for (; i < e; i++) {
        int c = g_col[i];
        float4 v = bf4_load(&in[(size_t)c * 128 + lane * 4]);
        a0.x += v.x; a0.y += v.y; a0.z += v.z; a0.w += v.w;
    }
    float inv = g_invdeg[n];
    r.x = (a0.x + a1.x + a2.x + a3.x) * inv;
    r.y = (a0.y + a1.y + a2.y + a3.y) * inv;
    r.z = (a0.z + a1.z + a2.z + a3.z) * inv;
    r.w = (a0.w + a1.w + a2.w + a3.w) * inv;
}

// ---------------- fused F4: agg_b2b (h_c) || agg_tflagged (ht) ---------------------
#define AGG_GRID 12500
__global__ void __launch_bounds__(256)
k_f4() {
    int b = blockIdx.x;
    int lane = threadIdx.x & 31;
    if (b < AGG_GRID) {
        // context: h_c = relu(agg(buf2 bf16)) -> buf4 bf16
        int n = b * 8 + (threadIdx.x >> 5);
        if (n >= N_NODES) return;
        float4 r;
        agg_node_bf16((const __nv_bfloat16*)g_buf2, n, lane, r);
        r.x = fmaxf(r.x, 0.f); r.y = fmaxf(r.y, 0.f);
        r.z = fmaxf(r.z, 0.f); r.w = fmaxf(r.w, 0.f);
        bf4_store(&((__nv_bfloat16*)g_buf4)[(size_t)n * 128 + lane * 4], r);
    } else {
        // target: ht = relu(agg(buf1 bf16)) at tflag nodes -> buf3 fp32
        int n = (b - AGG_GRID) * 8 + (threadIdx.x >> 5);
        if (n >= N_NODES) return;
        if (!g_tflag[n]) return;
        float4 r;
        agg_node_bf16((const __nv_bfloat16*)g_buf1, n, lane, r);
        r.x = fmaxf(r.x, 0.f); r.y = fmaxf(r.y, 0.f);
        r.z = fmaxf(r.z, 0.f); r.w = fmaxf(r.w, 0.f);
        *(float4*)&g_buf3[(size_t)n * 128 + lane * 4] = r;
    }
}

// ---------------- fused F5: agg_flagged (m) || agg_target --------------------------
#define F5_TGT ((T_NODES + 7) / 8)
__global__ void __launch_bounds__(256)
k_f5(const int* __restrict__ tgt) {
    int b = blockIdx.x;
    int lane = threadIdx.x & 31;
    if (b < AGG_GRID) {
        // m = agg(buf4 bf16) at flagged nodes -> buf1 fp32
        int n = b * 8 + (threadIdx.x >> 5);
        if (n >= N_NODES) return;
        if (!g_flag[n]) return;
        float4 r;
        agg_node_bf16((const __nv_bfloat16*)g_buf4, n, lane, r);
        *(float4*)&g_buf1[(size_t)n * 128 + lane * 4] = r;
    } else {
        // tbuf = agg(buf3)[targets]
        int t = (b - AGG_GRID) * 8 + (threadIdx.x >> 5);
        if (t >= T_NODES) return;
        int n = tgt[t];
        float4 r;
        agg_node(g_buf3, n, lane, r);
        *(float4*)&g_tbuf[(size_t)t * 128 + lane * 4] = r;
    }
}

// ---------------- fused predictor (tf32 MMA + ldmatrix, both layers) ---------------
#define FS_STR 140
#define WT_STR 36
#define HID_STR 260
#define PRED_SMEM_UINTS (64 * HID_STR + 128 * WT_STR)
#define PRED_SMEM (PRED_SMEM_UINTS * 4)

__global__ void __launch_bounds__(256)
k_pred(const float* __restrict__ m, const int* __restrict__ pair_s,
       const int* __restrict__ pair_t, const int* __restrict__ tgt,
       const float* __restrict__ mask, const float* __restrict__ Wp1,
       const float* __restrict__ Wp2, const float* __restrict__ bp2,
       float* __restrict__ out) {
    extern __shared__ unsigned sm[];
    int r0 = blockIdx.x * 64;
    int tid = threadIdx.x;
    __shared__ float ms[64];
    if (tid < 64) ms[tid] = mask[r0 + tid];
    int any = __syncthreads_or(tid < 64 && mask[r0 + tid] != 0.f);
    if (!any) {
        float4 zero = make_float4(0.f, 0.f, 0.f, 0.f);
#pragma unroll
        for (int i = 0; i < 8; i++) {
            int idx = tid + i * 256;
            *(float4*)&out[(size_t)r0 * 128 + idx * 4] = zero;
        }
        return;
    }

    unsigned* feats = sm;
    unsigned* wst   = sm + 64 * FS_STR;
    unsigned* hid   = sm;
    unsigned* ws2t  = sm + 64 * HID_STR;

    int lane = tid & 31, wid = tid >> 5;
    int wm = wid & 1, wn = wid >> 1;
    int gid = lane >> 2, tig = lane & 3;

    const unsigned* pfa = &feats[(wm * 32 + (lane & 15)) * FS_STR + ((lane >> 4) << 2)];
    const unsigned* pwb = &wst[(wn * 64 + ((lane >> 4) << 3) + (lane & 7)) * WT_STR +
                               (((lane >> 3) & 1) << 2)];
    const unsigned* pha = &hid[(wm * 32 + (lane & 15)) * HID_STR + ((lane >> 4) << 2)];
    const unsigned* pw2b = &ws2t[(wn * 32 + ((lane >> 4) << 3) + (lane & 7)) * WT_STR +
                                 (((lane >> 3) & 1) << 2)];

#pragma unroll
    for (int i = 0; i < 8; i++) {
        int idx = tid + i * 256;
        int r = idx >> 5, q = (idx & 31) << 2;
        int sN = pair_s[r0 + r];
        float4 v = *(const float4*)&m[(size_t)sN * 128 + q];
        uint4 u = make_uint4(f2tf(v.x), f2tf(v.y), f2tf(v.z), f2tf(v.w));
        *(uint4*)&feats[r * FS_STR + q] = u;
    }
    if (tid < 64) {
        int sN = pair_s[r0 + tid];
        int tN = tgt[pair_t[r0 + tid]];
        float4 ps = *(const float4*)&g_pe[sN * 4];
        float4 pt = *(const float4*)&g_pe[tN * 4];
        *(uint4*)&feats[tid * FS_STR + 128] =
            make_uint4(f2tf(ps.x), f2tf(ps.y), f2tf(ps.z), f2tf(ps.w));
        *(uint4*)&feats[tid * FS_STR + 132] =
            make_uint4(f2tf(pt.x), f2tf(pt.y), f2tf(pt.z), f2tf(pt.w));
    }

    float c[2][8][4];
#pragma unroll
    for (int mt = 0; mt < 2; mt++)
#pragma unroll
        for (int nt = 0; nt < 8; nt++)
#pragma unroll
            for (int q = 0; q < 4; q++) c[mt][nt][q] = 0.f;

    for (int ch = 0; ch < 5; ch++) {
        int nrows = (ch < 4) ? 32 : 8;
        {
            int n = tid;
            int nq = nrows >> 2;
#pragma unroll
            for (int q = 0; q < 8; q++) {
                if (q >= nq) break;
                int kk = q * 4;
                uint4 u;
                if (ch < 4) {
                    const float* base = &g_wf[(size_t)(ch * 32 + kk) * 256 + n];
                    u.x = f2tf(base[0]);
                    u.y = f2tf(base[256]);
                    u.z = f2tf(base[512]);
                    u.w = f2tf(base[768]);
                } else {
                    const float* base = &Wp1[(size_t)(192 + kk) * 256 + n];
                    u.x = f2tf(base[0]);
                    u.y = f2tf(base[256]);
                    u.z = f2tf(base[512]);
                    u.w = f2tf(base[768]);
                }
                *(uint4*)&wst[n * WT_STR + kk] = u;
            }
        }
        __syncthreads();
        int nks = nrows >> 3;
        for (int ks = 0; ks < nks; ks++) {
            int kb = ch * 32 + ks * 8;
            int kl = ks * 8;
            unsigned a[2][4], b[8][2];
            ldsm4(a[0], pfa + kb);
            ldsm4(a[1], pfa + 16 * FS_STR + kb);
#pragma unroll
            for (int p = 0; p < 4; p++) {
                unsigned t4[4];
                ldsm4(t4, pwb + p * 16 * WT_STR + kl);
                b[2 * p][0] = t4[0]; b[2 * p][1] = t4[1];
                b[2 * p + 1][0] = t4[2]; b[2 * p + 1][1] = t4[3];
            }
#pragma unroll
            for (int mt = 0; mt < 2; mt++)
#pragma unroll
                for (int nt = 0; nt < 8; nt++) mma8(c[mt][nt], a[mt], b[nt]);
        }
        __syncthreads();
    }

#pragma unroll
    for (int mt = 0; mt < 2; mt++) {
        int r = wm * 32 + mt * 16 + gid;
#pragma unroll
        for (int nt = 0; nt < 8; nt++) {
            int col = wn * 64 + nt * 8 + 2 * tig;
            float2 zbv = *(const float2*)&g_zb[col];
            uint2 u0 = make_uint2(f2tf(fmaxf(c[mt][nt][0] + zbv.x, 0.f)),
                                  f2tf(fmaxf(c[mt][nt][1] + zbv.y, 0.f)));
            uint2 u1 = make_uint2(f2tf(fmaxf(c[mt][nt][2] + zbv.x, 0.f)),
                                  f2tf(fmaxf(c[mt][nt][3] + zbv.y, 0.f)));
            *(uint2*)&hid[r * HID_STR + col] = u0;
            *(uint2*)&hid[(r + 8) * HID_STR + col] = u1;
        }
    }
    __syncthreads();

    float c2[2][4][4];
#pragma unroll
    for (int mt = 0; mt < 2; mt++)
#pragma unroll
        for (int nt = 0; nt < 4; nt++)
#pragma unroll
            for (int q = 0; q < 4; q++) c2[mt][nt][q] = 0.f;

    int w2n = tid & 127, w2kh = (tid >> 7) * 16;
    for (int ch = 0; ch < 8; ch++) {
        {
#pragma unroll
            for (int q = 0; q < 4; q++) {
                int kk = w2kh + q * 4;
                const float* base = &Wp2[(size_t)(ch * 32 + kk) * 128 + w2n];
                uint4 u;
                u.x = f2tf(base[0]);
                u.y = f2tf(base[128]);
                u.z = f2tf(base[256]);
                u.w = f2tf(base[384]);
                *(uint4*)&ws2t[w2n * WT_STR + kk] = u;
            }
        }
        __syncthreads();
#pragma unroll
        for (int ks = 0; ks < 4; ks++) {
            int kb = ch * 32 + ks * 8;
            int kl = ks * 8;
            unsigned a[2][4], b[4][2];
            ldsm4(a[0], pha + kb);
            ldsm4(a[1], pha + 16 * HID_STR + kb);
#pragma unroll
            for (int p = 0; p < 2; p++) {
                unsigned t4[4];
                ldsm4(t4, pw2b + p * 16 * WT_STR + kl);
                b[2 * p][0] = t4[0]; b[2 * p][1] = t4[1];
                b[2 * p + 1][0] = t4[2]; b[2 * p + 1][1] = t4[3];
            }
#pragma unroll
            for (int mt = 0; mt < 2; mt++)
#pragma unroll
                for (int nt = 0; nt < 4; nt++) mma8(c2[mt][nt], a[mt], b[nt]);
        }
        __syncthreads();
    }

#pragma unroll
    for (int mt = 0; mt < 2; mt++) {
        int lr = wm * 32 + mt * 16 + gid;
        float m0v = ms[lr], m1v = ms[lr + 8];
#pragma unroll
        for (int nt = 0; nt < 4; nt++) {
            int col = wn * 32 + nt * 8 + 2 * tig;
            float2 bb = *(const float2*)&bp2[col];
            float2 v0 = make_float2((c2[mt][nt][0] + bb.x) * m0v,
                                    (c2[mt][nt][1] + bb.y) * m0v);
            float2 v1 = make_float2((c2[mt][nt][2] + bb.x) * m1v,
                                    (c2[mt][nt][3] + bb.y) * m1v);
            *(float2*)&out[(size_t)(r0 + lr) * 128 + col] = v0;
            *(float2*)&out[(size_t)(r0 + lr + 8) * 128 + col] = v1;
        }
    }
}

// ---------------- launch ----------------
extern "C" void kernel_launch(void* const* d_in, const int* in_sizes, int n_in,
                              void* d_out, int out_size) {
    const float* x            = (const float*)d_in[0];
    const float* masked_x     = (const float*)d_in[1];
    const float* pos_enc      = (const float*)d_in[2];
    const int*   edge_src     = (const int*)d_in[3];
    const int*   edge_dst     = (const int*)d_in[4];
    const int*   target_nodes = (const int*)d_in[5];
    const int*   pair_t       = (const int*)d_in[6];
    const int*   pair_s       = (const int*)d_in[7];
    const float* pair_mask    = (const float*)d_in[8];
    const float* W1t          = (const float*)d_in[9];
    const float* W2t          = (const float*)d_in[10];
    const float* W1c          = (const float*)d_in[11];
    const float* W2c          = (const float*)d_in[12];
    const float* Wpe          = (const float*)d_in[13];
    const float* z            = (const float*)d_in[14];
    const float* Wp1          = (const float*)d_in[15];
    const float* bp1          = (const float*)d_in[16];
    const float* Wp2          = (const float*)d_in[17];
    const float* bp2          = (const float*)d_in[18];
    float* out = (float*)d_out;

    float *buf1, *tbuf;
    cudaGetSymbolAddress((void**)&buf1, g_buf1);
    cudaGetSymbolAddress((void**)&tbuf, g_tbuf);

    cudaFuncSetAttribute(k_pred, cudaFuncAttributeMaxDynamicSharedMemorySize,
                         PRED_SMEM);

    const int TPB = 256;

    // F1: gemm_t || zero(cnt/flag/tflag)
    k_f1<<<GM + F1_CSR, TPB>>>(x, W1t);
    // F2: gemm_c || count
    k_f2<<<GM + F2_CSR, TPB>>>(masked_x, W1c, edge_dst);
    // scan + prep
    k_scan<<<1, 1024>>>();
    k_prep<<<(N_NODES + TPB - 1) / TPB, TPB>>>();
    // F3: fill || pe || wf || zb || flag
    k_f3<<<F3_GRID, TPB>>>(edge_src, edge_dst, pos_enc, Wpe, W2c, Wp1, z, bp1,
                           pair_s, pair_mask);
    // tflag (needs fill)
    k_tflag<<<(T_NODES + TPB - 1) / TPB, TPB>>>(target_nodes);
    // F4: h_c agg || ht agg
    k_f4<<<AGG_GRID * 2, TPB>>>();
    // F5: m agg || target agg
    k_f5<<<AGG_GRID + F5_TGT, TPB>>>(target_nodes);
    // target tail: tiny GEMM straight into output embeddings
    k_gemm_tf32<<<T_NODES / 128, TPB>>>(tbuf, W2t, out + (size_t)P_PAIRS * DOUT,
                                        T_NODES, 0, 0);
    // fused predictor MLP
    k_pred<<<P_PAIRS / 64, TPB, PRED_SMEM>>>(buf1, pair_s, pair_t, target_nodes,
                                             pair_mask, Wp1, Wp2, bp2, out);
}